// round 1
// baseline (speedup 1.0000x reference)
#include <cuda_runtime.h>
#include <math.h>

#define B_    32
#define N_    32
#define E_    128
#define CIN_  64
#define COUT_ 128
#define H_    128
#define W_    128
#define KTOT  576   // CIN * 3 * 3

// Device scratch (no allocations allowed)
__device__ float g_out_node[B_ * N_ * COUT_];   // [B][N][COUT] attention result
__device__ float g_wt[KTOT * COUT_];            // weights transposed to [K][COUT]

// ---------------------------------------------------------------------------
// Kernel 1: transpose conv weights [COUT,CIN,3,3] -> [K=576][COUT]
// ---------------------------------------------------------------------------
__global__ void transpose_w_kernel(const float* __restrict__ conv_w) {
    int i = blockIdx.x * blockDim.x + threadIdx.x;   // i = k*128 + n
    if (i < KTOT * COUT_) {
        int k = i >> 7;
        int n = i & 127;
        g_wt[i] = conv_w[n * KTOT + k];
    }
}

// ---------------------------------------------------------------------------
// Kernel 2: per-batch node attention -> g_out_node
// One block per batch, 256 threads. Weights staged through smem in f-chunks.
// ---------------------------------------------------------------------------
#define ATT_SMEM_FLOATS (8192 + 3*8192 + 3*4096 + 1024 + 4096)  // 50176

__global__ void attn_kernel(const float* __restrict__ node_embeds,
                            const float* __restrict__ goal_embed,
                            const float* __restrict__ wQ,
                            const float* __restrict__ wK,
                            const float* __restrict__ wV,
                            const float* __restrict__ final_w,
                            const float* __restrict__ final_b) {
    extern __shared__ float sm[];
    float* x_s  = sm;                 // [32][256]
    float* wq_c = sm + 8192;          // [64][128] chunk
    float* wk_c = wq_c + 8192;
    float* wv_c = wk_c + 8192;
    float* q_s  = wv_c + 8192;        // [32][128]
    float* k_s  = q_s + 4096;
    float* v_s  = k_s + 4096;
    float* p_s  = v_s + 4096;         // [32][32]
    float* a_s  = p_s + 1024;         // [32][128]

    const int b = blockIdx.x;
    const int tid = threadIdx.x;

    // Phase 0: build x = concat(node_embeds[n], goal_embed[b]) in smem
    for (int i = tid; i < 32 * 256; i += 256) {
        int n = i >> 8, f = i & 255;
        x_s[i] = (f < 128) ? node_embeds[n * 128 + f]
                           : goal_embed[b * 128 + (f - 128)];
    }
    __syncthreads();

    // Phase 1: Q,K,V. thread owns (n = tid>>3, 16 consecutive k at kb)
    const int n  = tid >> 3;
    const int kb = (tid & 7) * 16;
    float aq[16], ak[16], av[16];
#pragma unroll
    for (int j = 0; j < 16; j++) { aq[j] = 0.f; ak[j] = 0.f; av[j] = 0.f; }

    for (int c = 0; c < 4; c++) {
        const int f0 = c * 64;
        for (int i = tid; i < 64 * 128; i += 256) {
            int f = i >> 7, k = i & 127;
            wq_c[i] = wQ[(f0 + f) * 128 + k];
            wk_c[i] = wK[(f0 + f) * 128 + k];
            wv_c[i] = wV[(f0 + f) * 128 + k];
        }
        __syncthreads();
#pragma unroll 4
        for (int f = 0; f < 64; f++) {
            float xv = x_s[n * 256 + f0 + f];
            const float4* q4 = (const float4*)(wq_c + f * 128 + kb);
            const float4* k4 = (const float4*)(wk_c + f * 128 + kb);
            const float4* v4 = (const float4*)(wv_c + f * 128 + kb);
#pragma unroll
            for (int jj = 0; jj < 4; jj++) {
                float4 wq4 = q4[jj], wk4 = k4[jj], wv4 = v4[jj];
                aq[jj*4+0] += xv * wq4.x; aq[jj*4+1] += xv * wq4.y;
                aq[jj*4+2] += xv * wq4.z; aq[jj*4+3] += xv * wq4.w;
                ak[jj*4+0] += xv * wk4.x; ak[jj*4+1] += xv * wk4.y;
                ak[jj*4+2] += xv * wk4.z; ak[jj*4+3] += xv * wk4.w;
                av[jj*4+0] += xv * wv4.x; av[jj*4+1] += xv * wv4.y;
                av[jj*4+2] += xv * wv4.z; av[jj*4+3] += xv * wv4.w;
            }
        }
        __syncthreads();
    }
#pragma unroll
    for (int j = 0; j < 16; j++) {
        q_s[n * 128 + kb + j] = aq[j];
        k_s[n * 128 + kb + j] = ak[j];
        v_s[n * 128 + kb + j] = av[j];
    }
    __syncthreads();

    // Phase 2: scores[q][n'] = Q[q].K[n'] / sqrt(E)
    for (int i = 0; i < 4; i++) {
        int idx = tid + i * 256;          // 0..1023
        int q  = idx >> 5;
        int nn = idx & 31;
        const float4* qa = (const float4*)(q_s + q * 128);
        const float4* ka = (const float4*)(k_s + nn * 128);
        float s = 0.f;
#pragma unroll
        for (int t = 0; t < 32; t++) {
            float4 qv = qa[t], kv = ka[t];
            s += qv.x * kv.x + qv.y * kv.y + qv.z * kv.z + qv.w * kv.w;
        }
        p_s[idx] = s * 0.08838834764831845f;   // 1/sqrt(128)
    }
    __syncthreads();

    // Phase 3: softmax rows
    if (tid < 32) {
        float mx = -1e30f;
        for (int i = 0; i < 32; i++) mx = fmaxf(mx, p_s[tid * 32 + i]);
        float s = 0.f;
        for (int i = 0; i < 32; i++) {
            float ev = expf(p_s[tid * 32 + i] - mx);
            p_s[tid * 32 + i] = ev;
            s += ev;
        }
        float inv = 1.f / s;
        for (int i = 0; i < 32; i++) p_s[tid * 32 + i] *= inv;
    }
    __syncthreads();

    // Phase 4: atten = P @ V  (thread: q = tid>>3, 16 k's at kb)
    {
        float accv[16];
#pragma unroll
        for (int j = 0; j < 16; j++) accv[j] = 0.f;
        int q = tid >> 3;
        for (int nn = 0; nn < 32; nn++) {
            float pv = p_s[q * 32 + nn];
            const float4* vv = (const float4*)(v_s + nn * 128 + kb);
#pragma unroll
            for (int jj = 0; jj < 4; jj++) {
                float4 v4 = vv[jj];
                accv[jj*4+0] += pv * v4.x; accv[jj*4+1] += pv * v4.y;
                accv[jj*4+2] += pv * v4.z; accv[jj*4+3] += pv * v4.w;
            }
        }
#pragma unroll
        for (int j = 0; j < 16; j++) a_s[q * 128 + kb + j] = accv[j];
    }
    __syncthreads();

    // Phase 5: out_node = atten @ final_w^T + final_b
    {
        int q  = tid >> 3;
        int ob = (tid & 7) * 16;
        const float4* aa = (const float4*)(a_s + q * 128);
#pragma unroll 4
        for (int j = 0; j < 16; j++) {
            int o = ob + j;
            const float4* fw = (const float4*)(final_w + o * 128);
            float s = final_b[o];
#pragma unroll
            for (int t = 0; t < 32; t++) {
                float4 a4 = aa[t], w4 = fw[t];
                s += a4.x * w4.x + a4.y * w4.y + a4.z * w4.z + a4.w * w4.w;
            }
            g_out_node[(b * 32 + q) * 128 + o] = s;
        }
    }
}

// ---------------------------------------------------------------------------
// Kernel 3: fused conv-as-GEMM + bias + node gather + NCHW store
// Block = (h, b): one image row (M=128 pixels) x all 128 couts, K=576.
// 256 threads, 8x8 thread tiles, BK=8 single-buffered.
// ---------------------------------------------------------------------------
__global__ void __launch_bounds__(256)
conv_kernel(const float* __restrict__ state,
            const float* __restrict__ conv_b,
            const int*   __restrict__ board,
            const int*   __restrict__ char_to_node,
            float*       __restrict__ out) {
    __shared__ float As[8][128];
    __shared__ float Bs[8][128];

    const int h = blockIdx.x;
    const int b = blockIdx.y;
    const int tid = threadIdx.x;
    const int txm = tid & 15;     // m (pixel) direction
    const int txn = tid >> 4;     // n (cout)  direction

    float acc[8][8];
#pragma unroll
    for (int j = 0; j < 8; j++)
#pragma unroll
        for (int i = 0; i < 8; i++) acc[j][i] = 0.f;

    const float* state_b = state + (size_t)b * CIN_ * H_ * W_;

    for (int k0 = 0; k0 < KTOT; k0 += 8) {
#pragma unroll
        for (int i = 0; i < 4; i++) {
            int e = tid + i * 256;          // 0..1023
            int k = e >> 7;
            int m = e & 127;
            int kg = k0 + k;
            int cin = kg / 9;
            int r = kg - cin * 9;
            int dy = r / 3;
            int dx = r - dy * 3;
            int hi = h + dy - 1;
            int wi = m + dx - 1;
            float v = 0.f;
            if ((unsigned)hi < 128u && (unsigned)wi < 128u)
                v = state_b[(cin << 14) + (hi << 7) + wi];
            As[k][m] = v;
            Bs[k][m] = g_wt[kg * 128 + m];
        }
        __syncthreads();
#pragma unroll
        for (int kk = 0; kk < 8; kk++) {
            float a[8], bb[8];
            *(float4*)(a)     = *(const float4*)(&As[kk][txm * 4]);
            *(float4*)(a + 4) = *(const float4*)(&As[kk][64 + txm * 4]);
            *(float4*)(bb)    = *(const float4*)(&Bs[kk][txn * 4]);
            *(float4*)(bb + 4)= *(const float4*)(&Bs[kk][64 + txn * 4]);
#pragma unroll
            for (int j = 0; j < 8; j++)
#pragma unroll
                for (int i2 = 0; i2 < 8; i2++)
                    acc[j][i2] += bb[j] * a[i2];
        }
        __syncthreads();
    }

    // Epilogue: + bias + gathered node embedding, store NCHW
    int   nidx[8];
    float vmask[8];
    const int* brow = board + (b * 128 + h) * 128;
#pragma unroll
    for (int i = 0; i < 8; i++) {
        int m = (i < 4) ? (txm * 4 + i) : (64 + txm * 4 + i - 4);
        int bv = brow[m];
        bool ok = (bv >= 0) && (bv < N_);
        nidx[i]  = ok ? char_to_node[bv] : 0;
        vmask[i] = ok ? 1.f : 0.f;
    }
    const float* node_b = g_out_node + (size_t)b * 32 * 128;
#pragma unroll
    for (int j = 0; j < 8; j++) {
        int o = (j < 4) ? (txn * 4 + j) : (64 + txn * 4 + j - 4);
        float bo = conv_b[o];
        float4 v0, v1;
        v0.x = acc[j][0] + bo + vmask[0] * node_b[nidx[0] * 128 + o];
        v0.y = acc[j][1] + bo + vmask[1] * node_b[nidx[1] * 128 + o];
        v0.z = acc[j][2] + bo + vmask[2] * node_b[nidx[2] * 128 + o];
        v0.w = acc[j][3] + bo + vmask[3] * node_b[nidx[3] * 128 + o];
        v1.x = acc[j][4] + bo + vmask[4] * node_b[nidx[4] * 128 + o];
        v1.y = acc[j][5] + bo + vmask[5] * node_b[nidx[5] * 128 + o];
        v1.z = acc[j][6] + bo + vmask[6] * node_b[nidx[6] * 128 + o];
        v1.w = acc[j][7] + bo + vmask[7] * node_b[nidx[7] * 128 + o];
        float* orow = out + (((size_t)(b * 128 + o)) * 128 + h) * 128;
        *(float4*)(orow + txm * 4)      = v0;
        *(float4*)(orow + 64 + txm * 4) = v1;
    }
}

// ---------------------------------------------------------------------------
extern "C" void kernel_launch(void* const* d_in, const int* in_sizes, int n_in,
                              void* d_out, int out_size) {
    const int*   game_board   = (const int*)  d_in[0];
    const float* state        = (const float*)d_in[1];
    const float* node_embeds  = (const float*)d_in[2];
    const float* goal_embed   = (const float*)d_in[3];
    const int*   char_to_node = (const int*)  d_in[4];
    const float* conv_w       = (const float*)d_in[5];
    const float* conv_b       = (const float*)d_in[6];
    const float* wQ           = (const float*)d_in[7];
    const float* wK           = (const float*)d_in[8];
    const float* wV           = (const float*)d_in[9];
    const float* final_w      = (const float*)d_in[10];
    const float* final_b      = (const float*)d_in[11];
    float* out = (float*)d_out;

    const int att_smem = ATT_SMEM_FLOATS * (int)sizeof(float);   // ~200 KB
    cudaFuncSetAttribute(attn_kernel,
                         cudaFuncAttributeMaxDynamicSharedMemorySize, att_smem);

    transpose_w_kernel<<<(KTOT * COUT_ + 255) / 256, 256>>>(conv_w);
    attn_kernel<<<B_, 256, att_smem>>>(node_embeds, goal_embed,
                                       wQ, wK, wV, final_w, final_b);
    conv_kernel<<<dim3(H_, B_), 256>>>(state, conv_b, game_board,
                                       char_to_node, out);
}

// round 4
// speedup vs baseline: 2.3414x; 2.3414x over previous
#include <cuda_runtime.h>
#include <cuda_bf16.h>
#include <math.h>
#include <cstdint>

#define B_    32
#define N_    32
#define E_    128
#define CIN_  64
#define COUT_ 128
#define H_    128
#define W_    128

// ---------------------------------------------------------------------------
// Device scratch
// ---------------------------------------------------------------------------
__device__ float g_out_node[B_ * N_ * COUT_];                 // [B][N][COUT]
__device__ __nv_bfloat16 g_state_hi[B_ * H_ * W_ * CIN_];     // BHWC hi
__device__ __nv_bfloat16 g_state_lo[B_ * H_ * W_ * CIN_];     // BHWC lo
__device__ __nv_bfloat16 g_wt_hi[9 * COUT_ * CIN_];           // [kk][cout][cin]
__device__ __nv_bfloat16 g_wt_lo[9 * COUT_ * CIN_];

// ---------------------------------------------------------------------------
// Helpers
// ---------------------------------------------------------------------------
__device__ __forceinline__ uint32_t smem_u32(const void* p) {
    uint32_t a;
    asm("{ .reg .u64 t; cvta.to.shared.u64 t, %1; cvt.u32.u64 %0, t; }" : "=r"(a) : "l"(p));
    return a;
}
#define SWZ(o) ((o) ^ (((o) >> 3) & 0x70))

__device__ __forceinline__ void cp_async16(uint32_t dst, const void* src, uint32_t srcsize) {
    asm volatile("cp.async.cg.shared.global [%0], [%1], 16, %2;"
                 :: "r"(dst), "l"(src), "r"(srcsize) : "memory");
}
#define CP_COMMIT() asm volatile("cp.async.commit_group;" ::: "memory")

__device__ __forceinline__ void ldm_x4(uint32_t* r, uint32_t addr) {
    asm volatile("ldmatrix.sync.aligned.m8n8.x4.shared.b16 {%0,%1,%2,%3}, [%4];"
                 : "=r"(r[0]), "=r"(r[1]), "=r"(r[2]), "=r"(r[3]) : "r"(addr));
}
__device__ __forceinline__ void mma_bf16(float* c, const uint32_t* a,
                                         uint32_t b0, uint32_t b1) {
    asm volatile(
        "mma.sync.aligned.m16n8k16.row.col.f32.bf16.bf16.f32 "
        "{%0,%1,%2,%3}, {%4,%5,%6,%7}, {%8,%9}, {%0,%1,%2,%3};"
        : "+f"(c[0]), "+f"(c[1]), "+f"(c[2]), "+f"(c[3])
        : "r"(a[0]), "r"(a[1]), "r"(a[2]), "r"(a[3]), "r"(b0), "r"(b1));
}

// ---------------------------------------------------------------------------
// Kernel 1: split state fp32 NCHW -> bf16 hi/lo BHWC
// ---------------------------------------------------------------------------
__global__ void __launch_bounds__(256)
split_state_kernel(const float* __restrict__ state) {
    __shared__ float s[64][33];
    const int w0 = blockIdx.x * 32;
    const int hh = blockIdx.y;
    const int b  = blockIdx.z;
    const int tid = threadIdx.x;

    for (int i = tid; i < 64 * 32; i += 256) {
        int c = i >> 5, w = i & 31;
        s[c][w] = state[(((size_t)(b * 64 + c) * 128) + hh) * 128 + w0 + w];
    }
    __syncthreads();

    int w  = tid >> 3;
    int ck = tid & 7;
    union { __nv_bfloat16 h[8]; uint4 u; } ph, pl;
#pragma unroll
    for (int j = 0; j < 8; j++) {
        float x = s[ck * 8 + j][w];
        __nv_bfloat16 hv = __float2bfloat16_rn(x);
        __nv_bfloat16 lv = __float2bfloat16_rn(x - __bfloat162float(hv));
        ph.h[j] = hv;
        pl.h[j] = lv;
    }
    size_t o = (((size_t)(b * 128 + hh) * 128) + w0 + w) * 64 + ck * 8;
    *(uint4*)(g_state_hi + o) = ph.u;
    *(uint4*)(g_state_lo + o) = pl.u;
}

// ---------------------------------------------------------------------------
// Kernel 2: split + transpose weights [o][c][ky][kx] -> [kk][o][c] hi/lo
// ---------------------------------------------------------------------------
__global__ void split_w_kernel(const float* __restrict__ conv_w) {
    int i = blockIdx.x * blockDim.x + threadIdx.x;
    if (i < 9 * 128 * 64) {
        int kk = i >> 13;
        int r  = i & 8191;
        int o  = r >> 6;
        int c  = r & 63;
        float x = conv_w[(o * 64 + c) * 9 + kk];
        __nv_bfloat16 hv = __float2bfloat16_rn(x);
        g_wt_hi[i] = hv;
        g_wt_lo[i] = __float2bfloat16_rn(x - __bfloat162float(hv));
    }
}

// ---------------------------------------------------------------------------
// Kernel 3: node attention (fp32)
// ---------------------------------------------------------------------------
#define ATT_SMEM_FLOATS (8192 + 3*8192 + 3*4096 + 1024 + 4096)

__global__ void attn_kernel(const float* __restrict__ node_embeds,
                            const float* __restrict__ goal_embed,
                            const float* __restrict__ wQ,
                            const float* __restrict__ wK,
                            const float* __restrict__ wV,
                            const float* __restrict__ final_w,
                            const float* __restrict__ final_b) {
    extern __shared__ float sm[];
    float* x_s  = sm;
    float* wq_c = sm + 8192;
    float* wk_c = wq_c + 8192;
    float* wv_c = wk_c + 8192;
    float* q_s  = wv_c + 8192;
    float* k_s  = q_s + 4096;
    float* v_s  = k_s + 4096;
    float* p_s  = v_s + 4096;
    float* a_s  = p_s + 1024;

    const int b = blockIdx.x;
    const int tid = threadIdx.x;

    for (int i = tid; i < 32 * 256; i += 256) {
        int n = i >> 8, f = i & 255;
        x_s[i] = (f < 128) ? node_embeds[n * 128 + f]
                           : goal_embed[b * 128 + (f - 128)];
    }
    __syncthreads();

    const int n  = tid >> 3;
    const int kb = (tid & 7) * 16;
    float aq[16], ak[16], av[16];
#pragma unroll
    for (int j = 0; j < 16; j++) { aq[j] = 0.f; ak[j] = 0.f; av[j] = 0.f; }

    for (int c = 0; c < 4; c++) {
        const int f0 = c * 64;
        for (int i = tid; i < 64 * 128; i += 256) {
            int f = i >> 7, k = i & 127;
            wq_c[i] = wQ[(f0 + f) * 128 + k];
            wk_c[i] = wK[(f0 + f) * 128 + k];
            wv_c[i] = wV[(f0 + f) * 128 + k];
        }
        __syncthreads();
#pragma unroll 4
        for (int f = 0; f < 64; f++) {
            float xv = x_s[n * 256 + f0 + f];
            const float4* q4 = (const float4*)(wq_c + f * 128 + kb);
            const float4* k4 = (const float4*)(wk_c + f * 128 + kb);
            const float4* v4 = (const float4*)(wv_c + f * 128 + kb);
#pragma unroll
            for (int jj = 0; jj < 4; jj++) {
                float4 wq4 = q4[jj], wk4 = k4[jj], wv4 = v4[jj];
                aq[jj*4+0] += xv * wq4.x; aq[jj*4+1] += xv * wq4.y;
                aq[jj*4+2] += xv * wq4.z; aq[jj*4+3] += xv * wq4.w;
                ak[jj*4+0] += xv * wk4.x; ak[jj*4+1] += xv * wk4.y;
                ak[jj*4+2] += xv * wk4.z; ak[jj*4+3] += xv * wk4.w;
                av[jj*4+0] += xv * wv4.x; av[jj*4+1] += xv * wv4.y;
                av[jj*4+2] += xv * wv4.z; av[jj*4+3] += xv * wv4.w;
            }
        }
        __syncthreads();
    }
#pragma unroll
    for (int j = 0; j < 16; j++) {
        q_s[n * 128 + kb + j] = aq[j];
        k_s[n * 128 + kb + j] = ak[j];
        v_s[n * 128 + kb + j] = av[j];
    }
    __syncthreads();

    for (int i = 0; i < 4; i++) {
        int idx = tid + i * 256;
        int q  = idx >> 5;
        int nn = idx & 31;
        const float4* qa = (const float4*)(q_s + q * 128);
        const float4* ka = (const float4*)(k_s + nn * 128);
        float s = 0.f;
#pragma unroll
        for (int t = 0; t < 32; t++) {
            float4 qv = qa[t], kv = ka[t];
            s += qv.x * kv.x + qv.y * kv.y + qv.z * kv.z + qv.w * kv.w;
        }
        p_s[idx] = s * 0.08838834764831845f;
    }
    __syncthreads();

    if (tid < 32) {
        float mx = -1e30f;
        for (int i = 0; i < 32; i++) mx = fmaxf(mx, p_s[tid * 32 + i]);
        float s = 0.f;
        for (int i = 0; i < 32; i++) {
            float ev = expf(p_s[tid * 32 + i] - mx);
            p_s[tid * 32 + i] = ev;
            s += ev;
        }
        float inv = 1.f / s;
        for (int i = 0; i < 32; i++) p_s[tid * 32 + i] *= inv;
    }
    __syncthreads();

    {
        float accv[16];
#pragma unroll
        for (int j = 0; j < 16; j++) accv[j] = 0.f;
        int q = tid >> 3;
        for (int nn = 0; nn < 32; nn++) {
            float pv = p_s[q * 32 + nn];
            const float4* vv = (const float4*)(v_s + nn * 128 + kb);
#pragma unroll
            for (int jj = 0; jj < 4; jj++) {
                float4 v4 = vv[jj];
                accv[jj*4+0] += pv * v4.x; accv[jj*4+1] += pv * v4.y;
                accv[jj*4+2] += pv * v4.z; accv[jj*4+3] += pv * v4.w;
            }
        }
#pragma unroll
        for (int j = 0; j < 16; j++) a_s[q * 128 + kb + j] = accv[j];
    }
    __syncthreads();

    {
        int q  = tid >> 3;
        int ob = (tid & 7) * 16;
        const float4* aa = (const float4*)(a_s + q * 128);
#pragma unroll 4
        for (int j = 0; j < 16; j++) {
            int o = ob + j;
            const float4* fw = (const float4*)(final_w + o * 128);
            float s = final_b[o];
#pragma unroll
            for (int t = 0; t < 32; t++) {
                float4 a4 = aa[t], w4 = fw[t];
                s += a4.x * w4.x + a4.y * w4.y + a4.z * w4.z + a4.w * w4.w;
            }
            g_out_node[(b * 32 + q) * 128 + o] = s;
        }
    }
}

// ---------------------------------------------------------------------------
// Kernel 4: conv as bf16 mma.sync GEMM + fused epilogue.
// CTA = (h2, b): M=256 (2 output rows x 128 w), N=128 couts.
// K = 9 taps x 64 cin, hi/lo 3-term split.
// A: 4 input rows (hi/lo) hoisted into smem once (8 x 16KB).
// B: per-tap 32KB (hi+lo), double-buffered cp.async.
// 512 threads = 16 warps, warp tile 64x32, mma m16n8k16.
// ---------------------------------------------------------------------------
#define SMEM_A_OFF   0
#define SMEM_B_OFF   131072
#define SMEM_Z_OFF   196608
#define CONV_SMEM    196864
#define NODET_OFF    133120
#define NIDX_OFF     150016

__global__ void __launch_bounds__(512, 1)
conv_mma_kernel(const float* __restrict__ conv_b,
                const int*   __restrict__ board,
                const int*   __restrict__ c2n,
                float*       __restrict__ out) {
    extern __shared__ char smem[];
    const uint32_t sA = smem_u32(smem);
    const int h2  = blockIdx.x;
    const int b   = blockIdx.y;
    const int tid = threadIdx.x;
    const int lane = tid & 31;
    const int wid  = tid >> 5;
    const int wm = wid & 3;      // m-group (64 rows each)
    const int wn = wid >> 2;     // n-group (32 couts each)

    // zero row for OOB ldmatrix
    if (tid < 16) *(uint4*)(smem + SMEM_Z_OFF + tid * 16) = make_uint4(0, 0, 0, 0);

    // ---- stage A: 4 rows x hi/lo, 128KB ----
#pragma unroll
    for (int t = 0; t < 16; t++) {
        int i   = tid + t * 512;
        int buf = i >> 10;          // 0..7 : (r*2 + p)
        int j   = i & 1023;
        int r   = buf >> 1, p = buf & 1;
        int w   = j >> 3,  ck = j & 7;
        int hr  = 2 * h2 - 1 + r;
        uint32_t oksz = ((unsigned)hr < 128u) ? 16u : 0u;
        int hrc = hr < 0 ? 0 : (hr > 127 ? 127 : hr);
        const __nv_bfloat16* g = p ? g_state_lo : g_state_hi;
        const void* src = g + (((size_t)(b * 128 + hrc) * 128) + w) * 64 + ck * 8;
        uint32_t dst = sA + buf * 16384 + SWZ(w * 128 + ck * 16);
        cp_async16(dst, src, oksz);
    }
    // ---- stage B tap 0 ----
    {
#pragma unroll
        for (int t = 0; t < 4; t++) {
            int i = tid + t * 512;
            int p = i >> 10, j = i & 1023;
            int n = j >> 3, ck = j & 7;
            const __nv_bfloat16* g = p ? g_wt_lo : g_wt_hi;
            const void* src = g + n * 64 + ck * 8;
            uint32_t dst = sA + SMEM_B_OFF + p * 16384 + SWZ(n * 128 + ck * 16);
            cp_async16(dst, src, 16);
        }
    }
    CP_COMMIT();

    float c[64];
#pragma unroll
    for (int j = 0; j < 64; j++) c[j] = 0.f;

    // per-lane constants
    const int lrow = lane & 15;
    const uint32_t khA = (uint32_t)((lane >> 4) << 4);
    const int nrow = (lane & 7) | ((lane & 16) >> 1);
    const uint32_t khB = (uint32_t)(((lane >> 3) & 1) << 4);
    const int wb0 = (wm & 1) * 64 + lrow;
    const int rb0 = wm >> 1;
    const uint32_t zaddr = sA + SMEM_Z_OFF;
    int nbs[2];
#pragma unroll
    for (int nt2 = 0; nt2 < 2; nt2++) nbs[nt2] = wn * 32 + nt2 * 16 + nrow;

    for (int kk = 0; kk < 9; kk++) {
        if (kk < 8) {
            int nb = (kk + 1) & 1;
#pragma unroll
            for (int t = 0; t < 4; t++) {
                int i = tid + t * 512;
                int p = i >> 10, j = i & 1023;
                int n = j >> 3, ck = j & 7;
                const __nv_bfloat16* g = p ? g_wt_lo : g_wt_hi;
                const void* src = g + (kk + 1) * 8192 + n * 64 + ck * 8;
                uint32_t dst = sA + SMEM_B_OFF + nb * 32768 + p * 16384 + SWZ(n * 128 + ck * 16);
                cp_async16(dst, src, 16);
            }
            CP_COMMIT();
            asm volatile("cp.async.wait_group 1;" ::: "memory");
        } else {
            asm volatile("cp.async.wait_group 0;" ::: "memory");
        }
        __syncthreads();

        const int dy = kk / 3, dx = kk - dy * 3;
        uint32_t aHi[4], aLo[4], aXr[4];
#pragma unroll
        for (int mt = 0; mt < 4; mt++) {
            int wv = wb0 + mt * 16 + dx - 1;
            bool ok = (unsigned)wv < 128u;
            uint32_t base = sA + (uint32_t)(rb0 + dy) * 32768 + (uint32_t)wv * 128;
            aHi[mt] = ok ? base : zaddr;
            aLo[mt] = ok ? base + 16384 : zaddr;
            aXr[mt] = ok ? (uint32_t)((wv & 7) << 4) : 0u;
        }
        const uint32_t bB = sA + SMEM_B_OFF + (uint32_t)(kk & 1) * 32768;
        uint32_t bHi[2], bLo[2], bXr[2];
#pragma unroll
        for (int nt2 = 0; nt2 < 2; nt2++) {
            bHi[nt2] = bB + (uint32_t)nbs[nt2] * 128;
            bLo[nt2] = bHi[nt2] + 16384;
            bXr[nt2] = (uint32_t)((nbs[nt2] & 7) << 4);
        }

#pragma unroll
        for (int ks = 0; ks < 4; ks++) {
            const uint32_t kA = (uint32_t)(ks * 32) + khA;
            const uint32_t kB = (uint32_t)(ks * 32) + khB;
            uint32_t bh[8];
            ldm_x4(bh,     bHi[0] + (kB ^ bXr[0]));
            ldm_x4(bh + 4, bHi[1] + (kB ^ bXr[1]));
            uint32_t ah[16];
#pragma unroll
            for (int mt = 0; mt < 4; mt++)
                ldm_x4(ah + 4 * mt, aHi[mt] + (kA ^ aXr[mt]));
#pragma unroll
            for (int mt = 0; mt < 4; mt++)
#pragma unroll
                for (int nt = 0; nt < 4; nt++) {
                    int bi = (nt >> 1) * 4 + (nt & 1) * 2;
                    mma_bf16(c + (mt * 4 + nt) * 4, ah + 4 * mt, bh[bi], bh[bi + 1]);
                }
            uint32_t al[16];
#pragma unroll
            for (int mt = 0; mt < 4; mt++)
                ldm_x4(al + 4 * mt, aLo[mt] + (kA ^ aXr[mt]));
#pragma unroll
            for (int mt = 0; mt < 4; mt++)
#pragma unroll
                for (int nt = 0; nt < 4; nt++) {
                    int bi = (nt >> 1) * 4 + (nt & 1) * 2;
                    mma_bf16(c + (mt * 4 + nt) * 4, al + 4 * mt, bh[bi], bh[bi + 1]);
                }
            uint32_t bl[8];
            ldm_x4(bl,     bLo[0] + (kB ^ bXr[0]));
            ldm_x4(bl + 4, bLo[1] + (kB ^ bXr[1]));
#pragma unroll
            for (int mt = 0; mt < 4; mt++)
#pragma unroll
                for (int nt = 0; nt < 4; nt++) {
                    int bi = (nt >> 1) * 4 + (nt & 1) * 2;
                    mma_bf16(c + (mt * 4 + nt) * 4, ah + 4 * mt, bl[bi], bl[bi + 1]);
                }
        }
        __syncthreads();
    }

    // ---- epilogue: stage accums [o][m] (pad 260), gather, coalesced store ----
    float* acc_s  = (float*)smem;
    float* node_t = (float*)(smem + NODET_OFF);   // [o][n] pad 33
    int*   nidx_s = (int*)(smem + NIDX_OFF);      // [m]

#pragma unroll
    for (int mt = 0; mt < 4; mt++)
#pragma unroll
        for (int nt = 0; nt < 4; nt++) {
            int m = wm * 64 + mt * 16 + (lane >> 2);
            int o = wn * 32 + nt * 8 + 2 * (lane & 3);
            const float* cf = c + (mt * 4 + nt) * 4;
            acc_s[o * 260 + m]           = cf[0];
            acc_s[(o + 1) * 260 + m]     = cf[1];
            acc_s[o * 260 + m + 8]       = cf[2];
            acc_s[(o + 1) * 260 + m + 8] = cf[3];
        }

    for (int i = tid; i < 4096; i += 512) {
        int o = i & 127, n = i >> 7;
        node_t[o * 33 + n] = g_out_node[(b * 32 + n) * 128 + o];
    }
    if (tid < 256) {
        int hh = 2 * h2 + (tid >> 7), w = tid & 127;
        int bv = board[(b * 128 + hh) * 128 + w];
        nidx_s[tid] = (bv >= 0 && bv < 32) ? c2n[bv] : -1;
    }
    __syncthreads();

#pragma unroll
    for (int it = 0; it < 16; it++) {
        int row = wid + it * 16;          // 0..255
        int o = row >> 1, half = row & 1;
        int hh = 2 * h2 + half;
        float bo = conv_b[o];
        int m = half * 128 + 4 * lane;
        float4 a4 = *(const float4*)&acc_s[o * 260 + m];
        int4  nd  = *(const int4*)&nidx_s[m];
        const float* nr = node_t + o * 33;
        float4 v;
        v.x = a4.x + bo + (nd.x >= 0 ? nr[nd.x] : 0.f);
        v.y = a4.y + bo + (nd.y >= 0 ? nr[nd.y] : 0.f);
        v.z = a4.z + bo + (nd.z >= 0 ? nr[nd.z] : 0.f);
        v.w = a4.w + bo + (nd.w >= 0 ? nr[nd.w] : 0.f);
        *(float4*)(out + (((size_t)(b * 128 + o) * 128) + hh) * 128 + 4 * lane) = v;
    }
}

// ---------------------------------------------------------------------------
extern "C" void kernel_launch(void* const* d_in, const int* in_sizes, int n_in,
                              void* d_out, int out_size) {
    const int*   game_board   = (const int*)  d_in[0];
    const float* state        = (const float*)d_in[1];
    const float* node_embeds  = (const float*)d_in[2];
    const float* goal_embed   = (const float*)d_in[3];
    const int*   char_to_node = (const int*)  d_in[4];
    const float* conv_w       = (const float*)d_in[5];
    const float* conv_b       = (const float*)d_in[6];
    const float* wQ           = (const float*)d_in[7];
    const float* wK           = (const float*)d_in[8];
    const float* wV           = (const float*)d_in[9];
    const float* final_w      = (const float*)d_in[10];
    const float* final_b      = (const float*)d_in[11];
    float* out = (float*)d_out;

    const int att_smem = ATT_SMEM_FLOATS * (int)sizeof(float);
    cudaFuncSetAttribute(attn_kernel,
                         cudaFuncAttributeMaxDynamicSharedMemorySize, att_smem);
    cudaFuncSetAttribute(conv_mma_kernel,
                         cudaFuncAttributeMaxDynamicSharedMemorySize, CONV_SMEM);

    split_state_kernel<<<dim3(4, 128, 32), 256>>>(state);
    split_w_kernel<<<(9 * 128 * 64 + 255) / 256, 256>>>(conv_w);
    attn_kernel<<<B_, 256, att_smem>>>(node_embeds, goal_embed,
                                       wQ, wK, wV, final_w, final_b);
    conv_mma_kernel<<<dim3(64, 32), 512, CONV_SMEM>>>(conv_b, game_board,
                                                      char_to_node, out);
}

// round 6
// speedup vs baseline: 3.4625x; 1.4788x over previous
#include <cuda_runtime.h>
#include <cuda_fp16.h>
#include <math.h>
#include <cstdint>

#define B_    32
#define N_    32
#define E_    128
#define CIN_  64
#define COUT_ 128
#define H_    128
#define W_    128

// ---------------------------------------------------------------------------
// Device scratch
// ---------------------------------------------------------------------------
__device__ float g_out_node[B_ * N_ * COUT_];        // [B][N][COUT]
__device__ __half g_state_f16[B_ * H_ * W_ * CIN_];  // BHWC fp16
__device__ __half g_wt_f16[9 * COUT_ * CIN_];        // [kk][cout][cin] fp16

// ---------------------------------------------------------------------------
// Helpers
// ---------------------------------------------------------------------------
__device__ __forceinline__ uint32_t smem_u32(const void* p) {
    uint32_t a;
    asm("{ .reg .u64 t; cvta.to.shared.u64 t, %1; cvt.u32.u64 %0, t; }" : "=r"(a) : "l"(p));
    return a;
}
#define SWZ(o) ((o) ^ (((o) >> 3) & 0x70))

__device__ __forceinline__ void cp_async16(uint32_t dst, const void* src, uint32_t srcsize) {
    asm volatile("cp.async.cg.shared.global [%0], [%1], 16, %2;"
                 :: "r"(dst), "l"(src), "r"(srcsize) : "memory");
}
#define CP_COMMIT() asm volatile("cp.async.commit_group;" ::: "memory")

__device__ __forceinline__ void ldm_x4(uint32_t* r, uint32_t addr) {
    asm volatile("ldmatrix.sync.aligned.m8n8.x4.shared.b16 {%0,%1,%2,%3}, [%4];"
                 : "=r"(r[0]), "=r"(r[1]), "=r"(r[2]), "=r"(r[3]) : "r"(addr));
}
__device__ __forceinline__ void mma_fp16(float* c, const uint32_t* a,
                                         uint32_t b0, uint32_t b1) {
    asm volatile(
        "mma.sync.aligned.m16n8k16.row.col.f32.f16.f16.f32 "
        "{%0,%1,%2,%3}, {%4,%5,%6,%7}, {%8,%9}, {%0,%1,%2,%3};"
        : "+f"(c[0]), "+f"(c[1]), "+f"(c[2]), "+f"(c[3])
        : "r"(a[0]), "r"(a[1]), "r"(a[2]), "r"(a[3]), "r"(b0), "r"(b1));
}

// ---------------------------------------------------------------------------
// Kernel 1: state fp32 NCHW -> fp16 BHWC
// ---------------------------------------------------------------------------
__global__ void __launch_bounds__(256)
split_state_kernel(const float* __restrict__ state) {
    __shared__ float s[64][33];
    const int w0 = blockIdx.x * 32;
    const int hh = blockIdx.y;
    const int b  = blockIdx.z;
    const int tid = threadIdx.x;

    for (int i = tid; i < 64 * 32; i += 256) {
        int c = i >> 5, w = i & 31;
        s[c][w] = state[(((size_t)(b * 64 + c) * 128) + hh) * 128 + w0 + w];
    }
    __syncthreads();

    int w  = tid >> 3;
    int ck = tid & 7;
    union { __half h[8]; uint4 u; } ph;
#pragma unroll
    for (int j = 0; j < 8; j++) ph.h[j] = __float2half_rn(s[ck * 8 + j][w]);
    size_t o = (((size_t)(b * 128 + hh) * 128) + w0 + w) * 64 + ck * 8;
    *(uint4*)(g_state_f16 + o) = ph.u;
}

// ---------------------------------------------------------------------------
// Kernel 2: weights [o][c][ky][kx] -> [kk][o][c] fp16
// ---------------------------------------------------------------------------
__global__ void split_w_kernel(const float* __restrict__ conv_w) {
    int i = blockIdx.x * blockDim.x + threadIdx.x;
    if (i < 9 * 128 * 64) {
        int kk = i >> 13;
        int r  = i & 8191;
        int o  = r >> 6;
        int c  = r & 63;
        g_wt_f16[i] = __float2half_rn(conv_w[(o * 64 + c) * 9 + kk]);
    }
}

// ---------------------------------------------------------------------------
// Kernel 3: node attention (fp32, exact)
// ---------------------------------------------------------------------------
#define ATT_SMEM_FLOATS (8192 + 3*8192 + 3*4096 + 1024 + 4096)

__global__ void attn_kernel(const float* __restrict__ node_embeds,
                            const float* __restrict__ goal_embed,
                            const float* __restrict__ wQ,
                            const float* __restrict__ wK,
                            const float* __restrict__ wV,
                            const float* __restrict__ final_w,
                            const float* __restrict__ final_b) {
    extern __shared__ float sm[];
    float* x_s  = sm;
    float* wq_c = sm + 8192;
    float* wk_c = wq_c + 8192;
    float* wv_c = wk_c + 8192;
    float* q_s  = wv_c + 8192;
    float* k_s  = q_s + 4096;
    float* v_s  = k_s + 4096;
    float* p_s  = v_s + 4096;
    float* a_s  = p_s + 1024;

    const int b = blockIdx.x;
    const int tid = threadIdx.x;

    for (int i = tid; i < 32 * 256; i += 256) {
        int n = i >> 8, f = i & 255;
        x_s[i] = (f < 128) ? node_embeds[n * 128 + f]
                           : goal_embed[b * 128 + (f - 128)];
    }
    __syncthreads();

    const int n  = tid >> 3;
    const int kb = (tid & 7) * 16;
    float aq[16], ak[16], av[16];
#pragma unroll
    for (int j = 0; j < 16; j++) { aq[j] = 0.f; ak[j] = 0.f; av[j] = 0.f; }

    for (int c = 0; c < 4; c++) {
        const int f0 = c * 64;
        for (int i = tid; i < 64 * 128; i += 256) {
            int f = i >> 7, k = i & 127;
            wq_c[i] = wQ[(f0 + f) * 128 + k];
            wk_c[i] = wK[(f0 + f) * 128 + k];
            wv_c[i] = wV[(f0 + f) * 128 + k];
        }
        __syncthreads();
#pragma unroll 4
        for (int f = 0; f < 64; f++) {
            float xv = x_s[n * 256 + f0 + f];
            const float4* q4 = (const float4*)(wq_c + f * 128 + kb);
            const float4* k4 = (const float4*)(wk_c + f * 128 + kb);
            const float4* v4 = (const float4*)(wv_c + f * 128 + kb);
#pragma unroll
            for (int jj = 0; jj < 4; jj++) {
                float4 wq4 = q4[jj], wk4 = k4[jj], wv4 = v4[jj];
                aq[jj*4+0] += xv * wq4.x; aq[jj*4+1] += xv * wq4.y;
                aq[jj*4+2] += xv * wq4.z; aq[jj*4+3] += xv * wq4.w;
                ak[jj*4+0] += xv * wk4.x; ak[jj*4+1] += xv * wk4.y;
                ak[jj*4+2] += xv * wk4.z; ak[jj*4+3] += xv * wk4.w;
                av[jj*4+0] += xv * wv4.x; av[jj*4+1] += xv * wv4.y;
                av[jj*4+2] += xv * wv4.z; av[jj*4+3] += xv * wv4.w;
            }
        }
        __syncthreads();
    }
#pragma unroll
    for (int j = 0; j < 16; j++) {
        q_s[n * 128 + kb + j] = aq[j];
        k_s[n * 128 + kb + j] = ak[j];
        v_s[n * 128 + kb + j] = av[j];
    }
    __syncthreads();

    for (int i = 0; i < 4; i++) {
        int idx = tid + i * 256;
        int q  = idx >> 5;
        int nn = idx & 31;
        const float4* qa = (const float4*)(q_s + q * 128);
        const float4* ka = (const float4*)(k_s + nn * 128);
        float s = 0.f;
#pragma unroll
        for (int t = 0; t < 32; t++) {
            float4 qv = qa[t], kv = ka[t];
            s += qv.x * kv.x + qv.y * kv.y + qv.z * kv.z + qv.w * kv.w;
        }
        p_s[idx] = s * 0.08838834764831845f;
    }
    __syncthreads();

    if (tid < 32) {
        float mx = -1e30f;
        for (int i = 0; i < 32; i++) mx = fmaxf(mx, p_s[tid * 32 + i]);
        float s = 0.f;
        for (int i = 0; i < 32; i++) {
            float ev = expf(p_s[tid * 32 + i] - mx);
            p_s[tid * 32 + i] = ev;
            s += ev;
        }
        float inv = 1.f / s;
        for (int i = 0; i < 32; i++) p_s[tid * 32 + i] *= inv;
    }
    __syncthreads();

    {
        float accv[16];
#pragma unroll
        for (int j = 0; j < 16; j++) accv[j] = 0.f;
        int q = tid >> 3;
        for (int nn = 0; nn < 32; nn++) {
            float pv = p_s[q * 32 + nn];
            const float4* vv = (const float4*)(v_s + nn * 128 + kb);
#pragma unroll
            for (int jj = 0; jj < 4; jj++) {
                float4 v4 = vv[jj];
                accv[jj*4+0] += pv * v4.x; accv[jj*4+1] += pv * v4.y;
                accv[jj*4+2] += pv * v4.z; accv[jj*4+3] += pv * v4.w;
            }
        }
#pragma unroll
        for (int j = 0; j < 16; j++) a_s[q * 128 + kb + j] = accv[j];
    }
    __syncthreads();

    {
        int q  = tid >> 3;
        int ob = (tid & 7) * 16;
        const float4* aa = (const float4*)(a_s + q * 128);
#pragma unroll 4
        for (int j = 0; j < 16; j++) {
            int o = ob + j;
            const float4* fw = (const float4*)(final_w + o * 128);
            float s = final_b[o];
#pragma unroll
            for (int t = 0; t < 32; t++) {
                float4 a4 = aa[t], w4 = fw[t];
                s += a4.x * w4.x + a4.y * w4.y + a4.z * w4.z + a4.w * w4.w;
            }
            g_out_node[(b * 32 + q) * 128 + o] = s;
        }
    }
}

// ---------------------------------------------------------------------------
// Kernel 4: conv as fp16 mma.sync GEMM, all-taps-preloaded, barrier-free loop.
// CTA = (h2, b): M=256 (2 output rows x 128 w), N=128 couts, K = 9 x 64.
// SMEM: A (4 rows x 16KB = 64KB) + B (9 taps x 16KB = 144KB) + zero(256B).
// 512 threads = 16 warps, warp tile 64x32, mma m16n8k16 fp16->fp32.
// ---------------------------------------------------------------------------
#define SMEM_B_OFF   65536
#define SMEM_Z_OFF   212992
#define CONV_SMEM    213504
#define NODET_OFF    133120
#define NIDX_OFF     150016

__global__ void __launch_bounds__(512, 1)
conv_mma_kernel(const float* __restrict__ conv_b,
                const int*   __restrict__ board,
                const int*   __restrict__ c2n,
                float*       __restrict__ out) {
    extern __shared__ char smem[];
    const uint32_t sA = smem_u32(smem);
    const int h2  = blockIdx.x;
    const int b   = blockIdx.y;
    const int tid = threadIdx.x;
    const int lane = tid & 31;
    const int wid  = tid >> 5;
    const int wm = wid & 3;      // m-group (64 rows each)
    const int wn = wid >> 2;     // n-group (32 couts each)

    // zero region for OOB ldmatrix
    if (tid < 16) *(uint4*)(smem + SMEM_Z_OFF + tid * 16) = make_uint4(0, 0, 0, 0);

    // ---- stage A: 4 input rows, 64KB ----
#pragma unroll
    for (int t = 0; t < 8; t++) {
        int i = tid + t * 512;        // 0..4095
        int r = i >> 10;              // input row 0..3
        int j = i & 1023;
        int w = j >> 3, ck = j & 7;
        int hr = 2 * h2 - 1 + r;
        uint32_t oksz = ((unsigned)hr < 128u) ? 16u : 0u;
        int hrc = hr < 0 ? 0 : (hr > 127 ? 127 : hr);
        const void* src = g_state_f16 + (((size_t)(b * 128 + hrc) * 128) + w) * 64 + ck * 8;
        cp_async16(sA + r * 16384 + SWZ(w * 128 + ck * 16), src, oksz);
    }
    // ---- stage B tap 0 ----
#pragma unroll
    for (int t = 0; t < 2; t++) {
        int i = tid + t * 512;        // 0..1023
        int n = (i & 1023) >> 3, ck = i & 7;
        const void* src = g_wt_f16 + n * 64 + ck * 8;
        cp_async16(sA + SMEM_B_OFF + SWZ(n * 128 + ck * 16), src, 16);
    }
    CP_COMMIT();
    // ---- stage B taps 1..8 ----
#pragma unroll
    for (int t = 2; t < 18; t++) {
        int i = tid + t * 512;        // 1024..9215
        int kk = i >> 10;             // 1..8
        int j = i & 1023;
        int n = j >> 3, ck = j & 7;
        const void* src = g_wt_f16 + kk * 8192 + n * 64 + ck * 8;
        cp_async16(sA + SMEM_B_OFF + kk * 16384 + SWZ(n * 128 + ck * 16), src, 16);
    }
    CP_COMMIT();

    float c[64];
#pragma unroll
    for (int j = 0; j < 64; j++) c[j] = 0.f;

    // per-lane fragment constants
    const int lrow = lane & 15;
    const uint32_t khA = (uint32_t)((lane >> 4) << 4);
    const int nrow = (lane & 7) | ((lane & 16) >> 1);
    const uint32_t khB = (uint32_t)(((lane >> 3) & 1) << 4);
    const int wb0 = (wm & 1) * 64 + lrow;
    const int rb0 = wm >> 1;
    const uint32_t zaddr = sA + SMEM_Z_OFF;
    int nbs[2];
#pragma unroll
    for (int nt2 = 0; nt2 < 2; nt2++) nbs[nt2] = wn * 32 + nt2 * 16 + nrow;

    asm volatile("cp.async.wait_group 1;" ::: "memory");
    __syncthreads();

    for (int kk = 0; kk < 9; kk++) {
        if (kk == 1) {
            asm volatile("cp.async.wait_group 0;" ::: "memory");
            __syncthreads();
        }
        const int dy = kk / 3, dx = kk - dy * 3;
        uint32_t aHi[4], aXr[4];
#pragma unroll
        for (int mt = 0; mt < 4; mt++) {
            int wv = wb0 + mt * 16 + dx - 1;
            bool ok = (unsigned)wv < 128u;
            aHi[mt] = ok ? (sA + (uint32_t)(rb0 + dy) * 16384 + (uint32_t)wv * 128) : zaddr;
            aXr[mt] = ok ? (uint32_t)((wv & 7) << 4) : 0u;
        }
        const uint32_t bB = sA + SMEM_B_OFF + (uint32_t)kk * 16384;
        uint32_t bHi[2], bXr[2];
#pragma unroll
        for (int nt2 = 0; nt2 < 2; nt2++) {
            bHi[nt2] = bB + (uint32_t)nbs[nt2] * 128;
            bXr[nt2] = (uint32_t)((nbs[nt2] & 7) << 4);
        }

#pragma unroll
        for (int ks = 0; ks < 4; ks++) {
            const uint32_t kA = (uint32_t)(ks * 32) + khA;
            const uint32_t kB = (uint32_t)(ks * 32) + khB;
            uint32_t bh[8];
            ldm_x4(bh,     bHi[0] + (kB ^ bXr[0]));
            ldm_x4(bh + 4, bHi[1] + (kB ^ bXr[1]));
            uint32_t ah[16];
#pragma unroll
            for (int mt = 0; mt < 4; mt++)
                ldm_x4(ah + 4 * mt, aHi[mt] + (kA ^ aXr[mt]));
#pragma unroll
            for (int mt = 0; mt < 4; mt++)
#pragma unroll
                for (int nt = 0; nt < 4; nt++) {
                    int bi = (nt >> 1) * 4 + (nt & 1) * 2;
                    mma_fp16(c + (mt * 4 + nt) * 4, ah + 4 * mt, bh[bi], bh[bi + 1]);
                }
        }
    }
    __syncthreads();

    // ---- epilogue: stage accums [o][m] (pad 260), gather, coalesced store ----
    float* acc_s  = (float*)smem;
    float* node_t = (float*)(smem + NODET_OFF);   // [o][n] pad 33
    int*   nidx_s = (int*)(smem + NIDX_OFF);      // [m]

#pragma unroll
    for (int mt = 0; mt < 4; mt++)
#pragma unroll
        for (int nt = 0; nt < 4; nt++) {
            int m = wm * 64 + mt * 16 + (lane >> 2);
            int o = wn * 32 + nt * 8 + 2 * (lane & 3);
            const float* cf = c + (mt * 4 + nt) * 4;
            acc_s[o * 260 + m]           = cf[0];
            acc_s[(o + 1) * 260 + m]     = cf[1];
            acc_s[o * 260 + m + 8]       = cf[2];
            acc_s[(o + 1) * 260 + m + 8] = cf[3];
        }

    for (int i = tid; i < 4096; i += 512) {
        int o = i & 127, n = i >> 7;
        node_t[o * 33 + n] = g_out_node[(b * 32 + n) * 128 + o];
    }
    if (tid < 256) {
        int hh = 2 * h2 + (tid >> 7), w = tid & 127;
        int bv = board[(b * 128 + hh) * 128 + w];
        nidx_s[tid] = (bv >= 0 && bv < 32) ? c2n[bv] : -1;
    }
    __syncthreads();

#pragma unroll
    for (int it = 0; it < 16; it++) {
        int row = wid + it * 16;          // 0..255
        int o = row >> 1, half = row & 1;
        int hh = 2 * h2 + half;
        float bo = conv_b[o];
        int m = half * 128 + 4 * lane;
        float4 a4 = *(const float4*)&acc_s[o * 260 + m];
        int4  nd  = *(const int4*)&nidx_s[m];
        const float* nr = node_t + o * 33;
        float4 v;
        v.x = a4.x + bo + (nd.x >= 0 ? nr[nd.x] : 0.f);
        v.y = a4.y + bo + (nd.y >= 0 ? nr[nd.y] : 0.f);
        v.z = a4.z + bo + (nd.z >= 0 ? nr[nd.z] : 0.f);
        v.w = a4.w + bo + (nd.w >= 0 ? nr[nd.w] : 0.f);
        *(float4*)(out + (((size_t)(b * 128 + o) * 128) + hh) * 128 + 4 * lane) = v;
    }
}

// ---------------------------------------------------------------------------
extern "C" void kernel_launch(void* const* d_in, const int* in_sizes, int n_in,
                              void* d_out, int out_size) {
    const int*   game_board   = (const int*)  d_in[0];
    const float* state        = (const float*)d_in[1];
    const float* node_embeds  = (const float*)d_in[2];
    const float* goal_embed   = (const float*)d_in[3];
    const int*   char_to_node = (const int*)  d_in[4];
    const float* conv_w       = (const float*)d_in[5];
    const float* conv_b       = (const float*)d_in[6];
    const float* wQ           = (const float*)d_in[7];
    const float* wK           = (const float*)d_in[8];
    const float* wV           = (const float*)d_in[9];
    const float* final_w      = (const float*)d_in[10];
    const float* final_b      = (const float*)d_in[11];
    float* out = (float*)d_out;

    const int att_smem = ATT_SMEM_FLOATS * (int)sizeof(float);
    cudaFuncSetAttribute(attn_kernel,
                         cudaFuncAttributeMaxDynamicSharedMemorySize, att_smem);
    cudaFuncSetAttribute(conv_mma_kernel,
                         cudaFuncAttributeMaxDynamicSharedMemorySize, CONV_SMEM);

    split_state_kernel<<<dim3(4, 128, 32), 256>>>(state);
    split_w_kernel<<<(9 * 128 * 64 + 255) / 256, 256>>>(conv_w);
    attn_kernel<<<B_, 256, att_smem>>>(node_embeds, goal_embed,
                                       wQ, wK, wV, final_w, final_b);
    conv_mma_kernel<<<dim3(64, 32), 512, CONV_SMEM>>>(conv_b, game_board,
                                                      char_to_node, out);
}

// round 8
// speedup vs baseline: 3.7979x; 1.0969x over previous
#include <cuda_runtime.h>
#include <cuda_fp16.h>
#include <math.h>
#include <cstdint>

#define B_    32
#define N_    32
#define E_    128
#define CIN_  64
#define COUT_ 128
#define H_    128
#define W_    128

// ---------------------------------------------------------------------------
// Device scratch
// ---------------------------------------------------------------------------
__device__ float g_out_node[B_ * N_ * COUT_];        // [B][N][COUT]
__device__ __half g_state_f16[B_ * H_ * W_ * CIN_];  // BHWC fp16
__device__ __half g_wt_f16[9 * COUT_ * CIN_];        // [kk][cout][cin] fp16

// ---------------------------------------------------------------------------
// Helpers
// ---------------------------------------------------------------------------
__device__ __forceinline__ uint32_t smem_u32(const void* p) {
    uint32_t a;
    asm("{ .reg .u64 t; cvta.to.shared.u64 t, %1; cvt.u32.u64 %0, t; }" : "=r"(a) : "l"(p));
    return a;
}
#define SWZ(o) ((o) ^ (((o) >> 3) & 0x70))

__device__ __forceinline__ void cp_async16(uint32_t dst, const void* src, uint32_t srcsize) {
    asm volatile("cp.async.cg.shared.global [%0], [%1], 16, %2;"
                 :: "r"(dst), "l"(src), "r"(srcsize) : "memory");
}
#define CP_COMMIT() asm volatile("cp.async.commit_group;" ::: "memory")

__device__ __forceinline__ void ldm_x4(uint32_t* r, uint32_t addr) {
    asm volatile("ldmatrix.sync.aligned.m8n8.x4.shared.b16 {%0,%1,%2,%3}, [%4];"
                 : "=r"(r[0]), "=r"(r[1]), "=r"(r[2]), "=r"(r[3]) : "r"(addr));
}
__device__ __forceinline__ void mma_fp16(float* c, const uint32_t* a,
                                         uint32_t b0, uint32_t b1) {
    asm volatile(
        "mma.sync.aligned.m16n8k16.row.col.f32.f16.f16.f32 "
        "{%0,%1,%2,%3}, {%4,%5,%6,%7}, {%8,%9}, {%0,%1,%2,%3};"
        : "+f"(c[0]), "+f"(c[1]), "+f"(c[2]), "+f"(c[3])
        : "r"(a[0]), "r"(a[1]), "r"(a[2]), "r"(a[3]), "r"(b0), "r"(b1));
}

// ---------------------------------------------------------------------------
// Kernel 1: state fp32 NCHW -> fp16 BHWC
// ---------------------------------------------------------------------------
__global__ void __launch_bounds__(256)
split_state_kernel(const float* __restrict__ state) {
    __shared__ float s[64][33];
    const int w0 = blockIdx.x * 32;
    const int hh = blockIdx.y;
    const int b  = blockIdx.z;
    const int tid = threadIdx.x;

    for (int i = tid; i < 64 * 32; i += 256) {
        int c = i >> 5, w = i & 31;
        s[c][w] = state[(((size_t)(b * 64 + c) * 128) + hh) * 128 + w0 + w];
    }
    __syncthreads();

    int w  = tid >> 3;
    int ck = tid & 7;
    union { __half h[8]; uint4 u; } ph;
#pragma unroll
    for (int j = 0; j < 8; j++) ph.h[j] = __float2half_rn(s[ck * 8 + j][w]);
    size_t o = (((size_t)(b * 128 + hh) * 128) + w0 + w) * 64 + ck * 8;
    *(uint4*)(g_state_f16 + o) = ph.u;
}

// ---------------------------------------------------------------------------
// Kernel 2: weights [o][c][ky][kx] -> [kk][o][c] fp16
// ---------------------------------------------------------------------------
__global__ void split_w_kernel(const float* __restrict__ conv_w) {
    int i = blockIdx.x * blockDim.x + threadIdx.x;
    if (i < 9 * 128 * 64) {
        int kk = i >> 13;
        int r  = i & 8191;
        int o  = r >> 6;
        int c  = r & 63;
        g_wt_f16[i] = __float2half_rn(conv_w[(o * 64 + c) * 9 + kk]);
    }
}

// ---------------------------------------------------------------------------
// Kernel 3: node attention (fp32, exact)
// ---------------------------------------------------------------------------
#define ATT_SMEM_FLOATS (8192 + 3*8192 + 3*4096 + 1024 + 4096)

__global__ void attn_kernel(const float* __restrict__ node_embeds,
                            const float* __restrict__ goal_embed,
                            const float* __restrict__ wQ,
                            const float* __restrict__ wK,
                            const float* __restrict__ wV,
                            const float* __restrict__ final_w,
                            const float* __restrict__ final_b) {
    extern __shared__ float sm[];
    float* x_s  = sm;
    float* wq_c = sm + 8192;
    float* wk_c = wq_c + 8192;
    float* wv_c = wk_c + 8192;
    float* q_s  = wv_c + 8192;
    float* k_s  = q_s + 4096;
    float* v_s  = k_s + 4096;
    float* p_s  = v_s + 4096;
    float* a_s  = p_s + 1024;

    const int b = blockIdx.x;
    const int tid = threadIdx.x;

    for (int i = tid; i < 32 * 256; i += 256) {
        int n = i >> 8, f = i & 255;
        x_s[i] = (f < 128) ? node_embeds[n * 128 + f]
                           : goal_embed[b * 128 + (f - 128)];
    }
    __syncthreads();

    const int n  = tid >> 3;
    const int kb = (tid & 7) * 16;
    float aq[16], ak[16], av[16];
#pragma unroll
    for (int j = 0; j < 16; j++) { aq[j] = 0.f; ak[j] = 0.f; av[j] = 0.f; }

    for (int c = 0; c < 4; c++) {
        const int f0 = c * 64;
        // vectorized staging: 64x128 floats = 2048 float4 per matrix
        const float4* wq4p = (const float4*)(wQ + f0 * 128);
        const float4* wk4p = (const float4*)(wK + f0 * 128);
        const float4* wv4p = (const float4*)(wV + f0 * 128);
        for (int i = tid; i < 2048; i += 256) {
            ((float4*)wq_c)[i] = wq4p[i];
            ((float4*)wk_c)[i] = wk4p[i];
            ((float4*)wv_c)[i] = wv4p[i];
        }
        __syncthreads();
#pragma unroll 4
        for (int f = 0; f < 64; f++) {
            float xv = x_s[n * 256 + f0 + f];
            const float4* q4 = (const float4*)(wq_c + f * 128 + kb);
            const float4* k4 = (const float4*)(wk_c + f * 128 + kb);
            const float4* v4 = (const float4*)(wv_c + f * 128 + kb);
#pragma unroll
            for (int jj = 0; jj < 4; jj++) {
                float4 wq4 = q4[jj], wk4 = k4[jj], wv4 = v4[jj];
                aq[jj*4+0] += xv * wq4.x; aq[jj*4+1] += xv * wq4.y;
                aq[jj*4+2] += xv * wq4.z; aq[jj*4+3] += xv * wq4.w;
                ak[jj*4+0] += xv * wk4.x; ak[jj*4+1] += xv * wk4.y;
                ak[jj*4+2] += xv * wk4.z; ak[jj*4+3] += xv * wk4.w;
                av[jj*4+0] += xv * wv4.x; av[jj*4+1] += xv * wv4.y;
                av[jj*4+2] += xv * wv4.z; av[jj*4+3] += xv * wv4.w;
            }
        }
        __syncthreads();
    }
#pragma unroll
    for (int j = 0; j < 16; j++) {
        q_s[n * 128 + kb + j] = aq[j];
        k_s[n * 128 + kb + j] = ak[j];
        v_s[n * 128 + kb + j] = av[j];
    }
    __syncthreads();

    for (int i = 0; i < 4; i++) {
        int idx = tid + i * 256;
        int q  = idx >> 5;
        int nn = idx & 31;
        const float4* qa = (const float4*)(q_s + q * 128);
        const float4* ka = (const float4*)(k_s + nn * 128);
        float s = 0.f;
#pragma unroll
        for (int t = 0; t < 32; t++) {
            float4 qv = qa[t], kv = ka[t];
            s += qv.x * kv.x + qv.y * kv.y + qv.z * kv.z + qv.w * kv.w;
        }
        p_s[idx] = s * 0.08838834764831845f;
    }
    __syncthreads();

    if (tid < 32) {
        float mx = -1e30f;
        for (int i = 0; i < 32; i++) mx = fmaxf(mx, p_s[tid * 32 + i]);
        float s = 0.f;
        for (int i = 0; i < 32; i++) {
            float ev = expf(p_s[tid * 32 + i] - mx);
            p_s[tid * 32 + i] = ev;
            s += ev;
        }
        float inv = 1.f / s;
        for (int i = 0; i < 32; i++) p_s[tid * 32 + i] *= inv;
    }
    __syncthreads();

    {
        float accv[16];
#pragma unroll
        for (int j = 0; j < 16; j++) accv[j] = 0.f;
        int q = tid >> 3;
        for (int nn = 0; nn < 32; nn++) {
            float pv = p_s[q * 32 + nn];
            const float4* vv = (const float4*)(v_s + nn * 128 + kb);
#pragma unroll
            for (int jj = 0; jj < 4; jj++) {
                float4 v4 = vv[jj];
                accv[jj*4+0] += pv * v4.x; accv[jj*4+1] += pv * v4.y;
                accv[jj*4+2] += pv * v4.z; accv[jj*4+3] += pv * v4.w;
            }
        }
#pragma unroll
        for (int j = 0; j < 16; j++) a_s[q * 128 + kb + j] = accv[j];
    }
    __syncthreads();

    {
        int q  = tid >> 3;
        int ob = (tid & 7) * 16;
        const float4* aa = (const float4*)(a_s + q * 128);
#pragma unroll 4
        for (int j = 0; j < 16; j++) {
            int o = ob + j;
            const float4* fw = (const float4*)(final_w + o * 128);
            float s = final_b[o];
#pragma unroll
            for (int t = 0; t < 32; t++) {
                float4 a4 = aa[t], w4 = fw[t];
                s += a4.x * w4.x + a4.y * w4.y + a4.z * w4.z + a4.w * w4.w;
            }
            g_out_node[(b * 32 + q) * 128 + o] = s;
        }
    }
}

// ---------------------------------------------------------------------------
// Kernel 4: conv as fp16 mma.sync GEMM, 2 CTAs/SM for prologue overlap.
// CTA = (h, b): M=128 pixels (1 output row), N=128 couts, K = 9 x 64.
// SMEM: A (3 rows x 16KB = 48KB) + B double-buffer (2 x 16KB) + zero.
// 256 threads = 8 warps (wm 0..1 x wn 0..3), warp tile 64x32, m16n8k16.
// Regs: 128/thread -> 2 CTAs = full RF.
// ---------------------------------------------------------------------------
#define SMEM_B_OFF   49152
#define SMEM_Z_OFF   81920
#define CONV_SMEM    84992
#define NODET_OFF    67584
#define NIDX_OFF     84480

__global__ void __launch_bounds__(256, 2)
conv_mma_kernel(const float* __restrict__ conv_b,
                const int*   __restrict__ board,
                const int*   __restrict__ c2n,
                float*       __restrict__ out) {
    extern __shared__ char smem[];
    const uint32_t sA = smem_u32(smem);
    const int h   = blockIdx.x;
    const int b   = blockIdx.y;
    const int tid = threadIdx.x;
    const int lane = tid & 31;
    const int wid  = tid >> 5;
    const int wm = wid & 1;      // m-group (64 pixels each)
    const int wn = wid >> 1;     // n-group (32 couts each)

    // zero region for OOB ldmatrix
    if (tid < 16) *(uint4*)(smem + SMEM_Z_OFF + tid * 16) = make_uint4(0, 0, 0, 0);

    // ---- stage A: 3 input rows (h-1..h+1), 48KB ----
#pragma unroll
    for (int t = 0; t < 12; t++) {
        int i = tid + t * 256;        // 0..3071
        int r = i >> 10;              // 0..2
        int j = i & 1023;
        int w = j >> 3, ck = j & 7;
        int hr = h - 1 + r;
        uint32_t oksz = ((unsigned)hr < 128u) ? 16u : 0u;
        int hrc = hr < 0 ? 0 : (hr > 127 ? 127 : hr);
        const void* src = g_state_f16 + (((size_t)(b * 128 + hrc) * 128) + w) * 64 + ck * 8;
        cp_async16(sA + r * 16384 + SWZ(w * 128 + ck * 16), src, oksz);
    }
    // ---- stage B tap 0 into buf0 (same commit group as A) ----
#pragma unroll
    for (int t = 0; t < 4; t++) {
        int i = tid + t * 256;        // 0..1023
        int n = i >> 3, ck = i & 7;
        cp_async16(sA + SMEM_B_OFF + SWZ(n * 128 + ck * 16),
                   g_wt_f16 + n * 64 + ck * 8, 16);
    }
    CP_COMMIT();
    // ---- stage B tap 1 into buf1 ----
#pragma unroll
    for (int t = 0; t < 4; t++) {
        int i = tid + t * 256;
        int n = i >> 3, ck = i & 7;
        cp_async16(sA + SMEM_B_OFF + 16384 + SWZ(n * 128 + ck * 16),
                   g_wt_f16 + 8192 + n * 64 + ck * 8, 16);
    }
    CP_COMMIT();

    float c[64];
#pragma unroll
    for (int j = 0; j < 64; j++) c[j] = 0.f;

    // per-lane fragment constants
    const int lrow = lane & 15;
    const uint32_t khA = (uint32_t)((lane >> 4) << 4);
    const int nrow = (lane & 7) | ((lane & 16) >> 1);
    const uint32_t khB = (uint32_t)(((lane >> 3) & 1) << 4);
    const int wb0 = wm * 64 + lrow;
    const uint32_t zaddr = sA + SMEM_Z_OFF;
    int nbs[2];
#pragma unroll
    for (int nt2 = 0; nt2 < 2; nt2++) nbs[nt2] = wn * 32 + nt2 * 16 + nrow;

    asm volatile("cp.async.wait_group 1;" ::: "memory");   // A + B0 ready
    __syncthreads();

#pragma unroll
    for (int kk = 0; kk < 9; kk++) {
        const int dy = kk / 3, dx = kk - dy * 3;
        uint32_t aHi[4], aXr[4];
#pragma unroll
        for (int mt = 0; mt < 4; mt++) {
            int wv = wb0 + mt * 16 + dx - 1;
            bool ok = (unsigned)wv < 128u;
            aHi[mt] = ok ? (sA + (uint32_t)dy * 16384 + (uint32_t)wv * 128) : zaddr;
            aXr[mt] = ok ? (uint32_t)((wv & 7) << 4) : 0u;
        }
        const uint32_t bB = sA + SMEM_B_OFF + (uint32_t)(kk & 1) * 16384;
        uint32_t bHi[2], bXr[2];
#pragma unroll
        for (int nt2 = 0; nt2 < 2; nt2++) {
            bHi[nt2] = bB + (uint32_t)nbs[nt2] * 128;
            bXr[nt2] = (uint32_t)((nbs[nt2] & 7) << 4);
        }

#pragma unroll
        for (int ks = 0; ks < 4; ks++) {
            const uint32_t kA = (uint32_t)(ks * 32) + khA;
            const uint32_t kB = (uint32_t)(ks * 32) + khB;
            uint32_t bh[8];
            ldm_x4(bh,     bHi[0] + (kB ^ bXr[0]));
            ldm_x4(bh + 4, bHi[1] + (kB ^ bXr[1]));
            uint32_t ah[16];
#pragma unroll
            for (int mt = 0; mt < 4; mt++)
                ldm_x4(ah + 4 * mt, aHi[mt] + (kA ^ aXr[mt]));
#pragma unroll
            for (int mt = 0; mt < 4; mt++)
#pragma unroll
                for (int nt = 0; nt < 4; nt++) {
                    int bi = (nt >> 1) * 4 + (nt & 1) * 2;
                    mma_fp16(c + (mt * 4 + nt) * 4, ah + 4 * mt, bh[bi], bh[bi + 1]);
                }
        }

        // prefetch tap kk+2 into the buffer we just finished reading
        if (kk <= 6) {
            __syncthreads();        // all warps done reading buf kk&1
            const __half* src_base = g_wt_f16 + (kk + 2) * 8192;
            const uint32_t dst_base = sA + SMEM_B_OFF + (uint32_t)(kk & 1) * 16384;
#pragma unroll
            for (int t = 0; t < 4; t++) {
                int i = tid + t * 256;
                int n = i >> 3, ck = i & 7;
                cp_async16(dst_base + SWZ(n * 128 + ck * 16), src_base + n * 64 + ck * 8, 16);
            }
            CP_COMMIT();
        }
        if (kk < 8) {
            if (kk < 7) asm volatile("cp.async.wait_group 1;" ::: "memory");
            else        asm volatile("cp.async.wait_group 0;" ::: "memory");
            __syncthreads();        // tap kk+1 visible to all warps
        }
    }
    __syncthreads();

    // ---- epilogue: stage accums [o][m] pad 132, gather, coalesced store ----
    float* acc_s  = (float*)smem;                 // 128 x 132 floats = 67584B
    float* node_t = (float*)(smem + NODET_OFF);   // [o][n] pad 33 = 16896B
    int*   nidx_s = (int*)(smem + NIDX_OFF);      // 128 ints

#pragma unroll
    for (int mt = 0; mt < 4; mt++)
#pragma unroll
        for (int nt = 0; nt < 4; nt++) {
            int m = wm * 64 + mt * 16 + (lane >> 2);
            int o = wn * 32 + nt * 8 + 2 * (lane & 3);
            const float* cf = c + (mt * 4 + nt) * 4;
            acc_s[o * 132 + m]           = cf[0];
            acc_s[(o + 1) * 132 + m]     = cf[1];
            acc_s[o * 132 + m + 8]       = cf[2];
            acc_s[(o + 1) * 132 + m + 8] = cf[3];
        }

    for (int i = tid; i < 4096; i += 256) {
        int o = i & 127, n = i >> 7;
        node_t[o * 33 + n] = g_out_node[(b * 32 + n) * 128 + o];
    }
    if (tid < 128) {
        int bv = board[(b * 128 + h) * 128 + tid];
        nidx_s[tid] = (bv >= 0 && bv < 32) ? c2n[bv] : -1;
    }
    __syncthreads();

#pragma unroll
    for (int it = 0; it < 16; it++) {
        int o = wid + it * 8;             // 0..127
        float bo = conv_b[o];
        float4 a4 = *(const float4*)&acc_s[o * 132 + 4 * lane];
        int4  nd  = *(const int4*)&nidx_s[4 * lane];
        const float* nr = node_t + o * 33;
        float4 v;
        v.x = a4.x + bo + (nd.x >= 0 ? nr[nd.x] : 0.f);
        v.y = a4.y + bo + (nd.y >= 0 ? nr[nd.y] : 0.f);
        v.z = a4.z + bo + (nd.z >= 0 ? nr[nd.z] : 0.f);
        v.w = a4.w + bo + (nd.w >= 0 ? nr[nd.w] : 0.f);
        *(float4*)(out + (((size_t)(b * 128 + o) * 128) + h) * 128 + 4 * lane) = v;
    }
}

// ---------------------------------------------------------------------------
extern "C" void kernel_launch(void* const* d_in, const int* in_sizes, int n_in,
                              void* d_out, int out_size) {
    const int*   game_board   = (const int*)  d_in[0];
    const float* state        = (const float*)d_in[1];
    const float* node_embeds  = (const float*)d_in[2];
    const float* goal_embed   = (const float*)d_in[3];
    const int*   char_to_node = (const int*)  d_in[4];
    const float* conv_w       = (const float*)d_in[5];
    const float* conv_b       = (const float*)d_in[6];
    const float* wQ           = (const float*)d_in[7];
    const float* wK           = (const float*)d_in[8];
    const float* wV           = (const float*)d_in[9];
    const float* final_w      = (const float*)d_in[10];
    const float* final_b      = (const float*)d_in[11];
    float* out = (float*)d_out;

    const int att_smem = ATT_SMEM_FLOATS * (int)sizeof(float);
    cudaFuncSetAttribute(attn_kernel,
                         cudaFuncAttributeMaxDynamicSharedMemorySize, att_smem);
    cudaFuncSetAttribute(conv_mma_kernel,
                         cudaFuncAttributeMaxDynamicSharedMemorySize, CONV_SMEM);

    split_state_kernel<<<dim3(4, 128, 32), 256>>>(state);
    split_w_kernel<<<(9 * 128 * 64 + 255) / 256, 256>>>(conv_w);
    attn_kernel<<<B_, 256, att_smem>>>(node_embeds, goal_embed,
                                       wQ, wK, wV, final_w, final_b);
    conv_mma_kernel<<<dim3(128, 32), 256, CONV_SMEM>>>(conv_b, game_board,
                                                       char_to_node, out);
}

// round 9
// speedup vs baseline: 5.8274x; 1.5344x over previous
#include <cuda_runtime.h>
#include <cuda_fp16.h>
#include <math.h>
#include <cstdint>

#define B_    32
#define N_    32
#define E_    128
#define CIN_  64
#define COUT_ 128
#define H_    128
#define W_    128

// ---------------------------------------------------------------------------
// Device scratch
// ---------------------------------------------------------------------------
__device__ float g_out_node_t[B_ * COUT_ * N_];      // [b][o][n]
__device__ __half g_state_f16[B_ * H_ * W_ * CIN_];  // BHWC fp16
__device__ __half g_wt_f16[9 * COUT_ * CIN_];        // [kk][cout][cin] fp16
__device__ float g_Qn[N_ * E_];                      // node @ wQ_top
__device__ float g_Kn[N_ * E_];
__device__ float g_Vn[N_ * E_];
__device__ float g_S0[N_ * N_];                      // Qn @ Kn^T (unscaled)
__device__ float g_Vnf[N_ * COUT_];                  // Vn @ final_w^T

// ---------------------------------------------------------------------------
// Helpers
// ---------------------------------------------------------------------------
__device__ __forceinline__ uint32_t smem_u32(const void* p) {
    uint32_t a;
    asm("{ .reg .u64 t; cvta.to.shared.u64 t, %1; cvt.u32.u64 %0, t; }" : "=r"(a) : "l"(p));
    return a;
}
#define SWZ(o) ((o) ^ (((o) >> 3) & 0x70))

__device__ __forceinline__ void cp_async16(uint32_t dst, const void* src, uint32_t srcsize) {
    asm volatile("cp.async.cg.shared.global [%0], [%1], 16, %2;"
                 :: "r"(dst), "l"(src), "r"(srcsize) : "memory");
}
#define CP_COMMIT() asm volatile("cp.async.commit_group;" ::: "memory")

__device__ __forceinline__ void ldm_x4(uint32_t* r, uint32_t addr) {
    asm volatile("ldmatrix.sync.aligned.m8n8.x4.shared.b16 {%0,%1,%2,%3}, [%4];"
                 : "=r"(r[0]), "=r"(r[1]), "=r"(r[2]), "=r"(r[3]) : "r"(addr));
}
__device__ __forceinline__ void mma_fp16(float* c, const uint32_t* a,
                                         uint32_t b0, uint32_t b1) {
    asm volatile(
        "mma.sync.aligned.m16n8k16.row.col.f32.f16.f16.f32 "
        "{%0,%1,%2,%3}, {%4,%5,%6,%7}, {%8,%9}, {%0,%1,%2,%3};"
        : "+f"(c[0]), "+f"(c[1]), "+f"(c[2]), "+f"(c[3])
        : "r"(a[0]), "r"(a[1]), "r"(a[2]), "r"(a[3]), "r"(b0), "r"(b1));
}
__device__ __forceinline__ float dot4(float4 a, float4 b) {
    return a.x * b.x + a.y * b.y + a.z * b.z + a.w * b.w;
}

// ---------------------------------------------------------------------------
// Kernel 1: state fp32 NCHW -> fp16 BHWC
// ---------------------------------------------------------------------------
__global__ void __launch_bounds__(256)
split_state_kernel(const float* __restrict__ state) {
    __shared__ float s[64][33];
    const int w0 = blockIdx.x * 32;
    const int hh = blockIdx.y;
    const int b  = blockIdx.z;
    const int tid = threadIdx.x;

    for (int i = tid; i < 64 * 32; i += 256) {
        int c = i >> 5, w = i & 31;
        s[c][w] = state[(((size_t)(b * 64 + c) * 128) + hh) * 128 + w0 + w];
    }
    __syncthreads();

    int w  = tid >> 3;
    int ck = tid & 7;
    union { __half h[8]; uint4 u; } ph;
#pragma unroll
    for (int j = 0; j < 8; j++) ph.h[j] = __float2half_rn(s[ck * 8 + j][w]);
    size_t o = (((size_t)(b * 128 + hh) * 128) + w0 + w) * 64 + ck * 8;
    *(uint4*)(g_state_f16 + o) = ph.u;
}

// ---------------------------------------------------------------------------
// Kernel 2: weights [o][c][ky][kx] -> [kk][o][c] fp16
// ---------------------------------------------------------------------------
__global__ void split_w_kernel(const float* __restrict__ conv_w) {
    int i = blockIdx.x * blockDim.x + threadIdx.x;
    if (i < 9 * 128 * 64) {
        int kk = i >> 13;
        int r  = i & 8191;
        int o  = r >> 6;
        int c  = r & 63;
        g_wt_f16[i] = __float2half_rn(conv_w[(o * 64 + c) * 9 + kk]);
    }
}

// ---------------------------------------------------------------------------
// Kernel 3a: Qn/Kn/Vn = node @ w*_top  (batch-independent). grid 16 x 256.
// ---------------------------------------------------------------------------
__global__ void __launch_bounds__(256)
attn_pre1(const float* __restrict__ node_embeds,
          const float* __restrict__ wQ,
          const float* __restrict__ wK,
          const float* __restrict__ wV) {
    const int tid = threadIdx.x;
    const int n = blockIdx.x * 2 + (tid >> 7);
    const int k = tid & 127;
    float aq = 0.f, ak = 0.f, av = 0.f;
#pragma unroll 4
    for (int f = 0; f < 128; f++) {
        float nv = __ldg(&node_embeds[n * 128 + f]);
        aq += nv * __ldg(&wQ[f * 128 + k]);
        ak += nv * __ldg(&wK[f * 128 + k]);
        av += nv * __ldg(&wV[f * 128 + k]);
    }
    g_Qn[n * 128 + k] = aq;
    g_Kn[n * 128 + k] = ak;
    g_Vn[n * 128 + k] = av;
}

// ---------------------------------------------------------------------------
// Kernel 3b: S0 = Qn@Kn^T, Vnf = Vn@final_w^T. grid 5 x 256.
// ---------------------------------------------------------------------------
__global__ void __launch_bounds__(256)
attn_pre2(const float* __restrict__ final_w) {
    const int tid = threadIdx.x;
    if (blockIdx.x == 0) {
        int q = tid >> 3, n0 = (tid & 7) * 4;
#pragma unroll
        for (int j = 0; j < 4; j++) {
            int n = n0 + j;
            const float4* qa = (const float4*)(g_Qn + q * 128);
            const float4* ka = (const float4*)(g_Kn + n * 128);
            float s = 0.f;
#pragma unroll
            for (int t = 0; t < 32; t++) s += dot4(__ldg(&qa[t]), __ldg(&ka[t]));
            g_S0[q * 32 + n] = s;
        }
    } else {
        int n = tid >> 3;
        int ob = (blockIdx.x - 1) * 32 + (tid & 7) * 4;
#pragma unroll
        for (int j = 0; j < 4; j++) {
            int o = ob + j;
            const float4* va = (const float4*)(g_Vn + n * 128);
            const float4* fw = (const float4*)(final_w + o * 128);
            float s = 0.f;
#pragma unroll
            for (int t = 0; t < 32; t++) s += dot4(__ldg(&va[t]), __ldg(&fw[t]));
            g_Vnf[n * 128 + o] = s;
        }
    }
}

// ---------------------------------------------------------------------------
// Kernel 3c: per-batch attention corrections + output. grid 32 x 256.
// ---------------------------------------------------------------------------
__global__ void __launch_bounds__(256)
attn_perb(const float* __restrict__ goal_embed,
          const float* __restrict__ wQ,
          const float* __restrict__ wK,
          const float* __restrict__ wV,
          const float* __restrict__ final_w,
          const float* __restrict__ final_b) {
    __shared__ float sg[128], sqg[128], skg[128], svg[128];
    __shared__ float su[32], sv[32], ss0[1], svgf[128], sP[32 * 32];
    const int b = blockIdx.x;
    const int tid = threadIdx.x;

    if (tid < 128) sg[tid] = goal_embed[b * 128 + tid];
    __syncthreads();

    // qg / kg (256 threads), then vg (128 threads)
    {
        int k = tid & 127;
        const float* w = (tid >> 7) ? wK : wQ;
        float acc = 0.f;
#pragma unroll 4
        for (int f = 0; f < 128; f++) acc += sg[f] * __ldg(&w[(128 + f) * 128 + k]);
        ((tid >> 7) ? skg : sqg)[k] = acc;
    }
    if (tid < 128) {
        float acc = 0.f;
#pragma unroll 4
        for (int f = 0; f < 128; f++) acc += sg[f] * __ldg(&wV[(128 + f) * 128 + tid]);
        svg[tid] = acc;
    }
    __syncthreads();

    // u[q] = Qn[q].kg ; v[n] = qg.Kn[n] ; s = qg.kg ; vgf[o] = final_b[o]+vg.fw[o]
    if (tid < 32) {
        const float4* qa = (const float4*)(g_Qn + tid * 128);
        float a = 0.f;
#pragma unroll
        for (int t = 0; t < 32; t++) a += dot4(__ldg(&qa[t]), *(float4*)&skg[t * 4]);
        su[tid] = a;
    } else if (tid < 64) {
        const float4* ka = (const float4*)(g_Kn + (tid - 32) * 128);
        float a = 0.f;
#pragma unroll
        for (int t = 0; t < 32; t++) a += dot4(__ldg(&ka[t]), *(float4*)&sqg[t * 4]);
        sv[tid - 32] = a;
    } else if (tid == 64) {
        float a = 0.f;
#pragma unroll
        for (int t = 0; t < 32; t++) a += dot4(*(float4*)&sqg[t * 4], *(float4*)&skg[t * 4]);
        ss0[0] = a;
    } else if (tid >= 128) {
        int o = tid - 128;
        const float4* fw = (const float4*)(final_w + o * 128);
        float a = __ldg(&final_b[o]);
#pragma unroll
        for (int t = 0; t < 32; t++) a += dot4(*(float4*)&svg[t * 4], __ldg(&fw[t]));
        svgf[o] = a;
    }
    __syncthreads();

    // scores + softmax (rows)
    if (tid < 32) {
        const int q = tid;
        float mx = -1e30f;
#pragma unroll
        for (int n = 0; n < 32; n++) {
            float r = (__ldg(&g_S0[q * 32 + n]) + su[q] + sv[n] + ss0[0]) * 0.08838834764831845f;
            sP[q * 32 + n] = r;
            mx = fmaxf(mx, r);
        }
        float s = 0.f;
#pragma unroll
        for (int n = 0; n < 32; n++) {
            float e = expf(sP[q * 32 + n] - mx);
            sP[q * 32 + n] = e;
            s += e;
        }
        float inv = 1.f / s;
#pragma unroll
        for (int n = 0; n < 32; n++) sP[q * 32 + n] *= inv;
    }
    __syncthreads();

    // out_node_t[b][o][q] = P[q] . Vnf[:,o] + vgf[o]
    {
        int o = tid >> 1, q0 = (tid & 1) * 16;
#pragma unroll
        for (int qq = 0; qq < 16; qq++) {
            int q = q0 + qq;
            float a = svgf[o];
#pragma unroll
            for (int n = 0; n < 32; n++)
                a += sP[q * 32 + n] * __ldg(&g_Vnf[n * 128 + o]);
            g_out_node_t[b * 4096 + o * 32 + q] = a;
        }
    }
}

// ---------------------------------------------------------------------------
// Kernel 4: conv as fp16 mma.sync GEMM, 2 CTAs/SM, 3-stage B ring.
// CTA = (h, b): M=128 pixels, N=128 couts, K = 9 x 64.
// SMEM: A 48KB + B 3x16KB + zero. 256 threads, warp tile 64x32.
// ---------------------------------------------------------------------------
#define SMEM_B_OFF   49152
#define SMEM_Z_OFF   98304
#define CONV_SMEM    98560
#define NODET_OFF    67584
#define NIDX_OFF     84480

__global__ void __launch_bounds__(256, 2)
conv_mma_kernel(const float* __restrict__ conv_b,
                const int*   __restrict__ board,
                const int*   __restrict__ c2n,
                float*       __restrict__ out) {
    extern __shared__ char smem[];
    const uint32_t sA = smem_u32(smem);
    const int h   = blockIdx.x;
    const int b   = blockIdx.y;
    const int tid = threadIdx.x;
    const int lane = tid & 31;
    const int wid  = tid >> 5;
    const int wm = wid & 1;
    const int wn = wid >> 1;

    if (tid < 16) *(uint4*)(smem + SMEM_Z_OFF + tid * 16) = make_uint4(0, 0, 0, 0);

    // ---- stage A: 3 input rows (h-1..h+1) ----
#pragma unroll
    for (int t = 0; t < 12; t++) {
        int i = tid + t * 256;
        int r = i >> 10;
        int j = i & 1023;
        int w = j >> 3, ck = j & 7;
        int hr = h - 1 + r;
        uint32_t oksz = ((unsigned)hr < 128u) ? 16u : 0u;
        int hrc = hr < 0 ? 0 : (hr > 127 ? 127 : hr);
        const void* src = g_state_f16 + (((size_t)(b * 128 + hrc) * 128) + w) * 64 + ck * 8;
        cp_async16(sA + r * 16384 + SWZ(w * 128 + ck * 16), src, oksz);
    }
    // ---- B tap 0 -> buf0 (group 0, with A) ----
#pragma unroll
    for (int t = 0; t < 4; t++) {
        int i = tid + t * 256;
        int n = i >> 3, ck = i & 7;
        cp_async16(sA + SMEM_B_OFF + SWZ(n * 128 + ck * 16),
                   g_wt_f16 + n * 64 + ck * 8, 16);
    }
    CP_COMMIT();
    // ---- B tap 1 -> buf1 (group 1) ----
#pragma unroll
    for (int t = 0; t < 4; t++) {
        int i = tid + t * 256;
        int n = i >> 3, ck = i & 7;
        cp_async16(sA + SMEM_B_OFF + 16384 + SWZ(n * 128 + ck * 16),
                   g_wt_f16 + 8192 + n * 64 + ck * 8, 16);
    }
    CP_COMMIT();

    float c[64];
#pragma unroll
    for (int j = 0; j < 64; j++) c[j] = 0.f;

    const int lrow = lane & 15;
    const uint32_t khA = (uint32_t)((lane >> 4) << 4);
    const int nrow = (lane & 7) | ((lane & 16) >> 1);
    const uint32_t khB = (uint32_t)(((lane >> 3) & 1) << 4);
    const int wb0 = wm * 64 + lrow;
    const uint32_t zaddr = sA + SMEM_Z_OFF;
    int nbs[2];
#pragma unroll
    for (int nt2 = 0; nt2 < 2; nt2++) nbs[nt2] = wn * 32 + nt2 * 16 + nrow;

#pragma unroll
    for (int kk = 0; kk < 9; kk++) {
        // wait for tap kk's group (in-order completion); then one sync.
        if (kk < 8) asm volatile("cp.async.wait_group 1;" ::: "memory");
        else        asm volatile("cp.async.wait_group 0;" ::: "memory");
        __syncthreads();   // publishes tap kk; protects buf (kk+2)%3 (readers of kk-1 done)

        // prefetch tap kk+2 into buf (kk+2)%3
        if (kk <= 6) {
            const __half* src_base = g_wt_f16 + (kk + 2) * 8192;
            const uint32_t dst_base = sA + SMEM_B_OFF + (uint32_t)((kk + 2) % 3) * 16384;
#pragma unroll
            for (int t = 0; t < 4; t++) {
                int i = tid + t * 256;
                int n = i >> 3, ck = i & 7;
                cp_async16(dst_base + SWZ(n * 128 + ck * 16), src_base + n * 64 + ck * 8, 16);
            }
            CP_COMMIT();
        }

        const int dy = kk / 3, dx = kk - dy * 3;
        uint32_t aHi[4], aXr[4];
#pragma unroll
        for (int mt = 0; mt < 4; mt++) {
            int wv = wb0 + mt * 16 + dx - 1;
            bool ok = (unsigned)wv < 128u;
            aHi[mt] = ok ? (sA + (uint32_t)dy * 16384 + (uint32_t)wv * 128) : zaddr;
            aXr[mt] = ok ? (uint32_t)((wv & 7) << 4) : 0u;
        }
        const uint32_t bB = sA + SMEM_B_OFF + (uint32_t)(kk % 3) * 16384;
        uint32_t bHi[2], bXr[2];
#pragma unroll
        for (int nt2 = 0; nt2 < 2; nt2++) {
            bHi[nt2] = bB + (uint32_t)nbs[nt2] * 128;
            bXr[nt2] = (uint32_t)((nbs[nt2] & 7) << 4);
        }

#pragma unroll
        for (int ks = 0; ks < 4; ks++) {
            const uint32_t kA = (uint32_t)(ks * 32) + khA;
            const uint32_t kB = (uint32_t)(ks * 32) + khB;
            uint32_t bh[8];
            ldm_x4(bh,     bHi[0] + (kB ^ bXr[0]));
            ldm_x4(bh + 4, bHi[1] + (kB ^ bXr[1]));
            uint32_t ah[16];
#pragma unroll
            for (int mt = 0; mt < 4; mt++)
                ldm_x4(ah + 4 * mt, aHi[mt] + (kA ^ aXr[mt]));
#pragma unroll
            for (int mt = 0; mt < 4; mt++)
#pragma unroll
                for (int nt = 0; nt < 4; nt++) {
                    int bi = (nt >> 1) * 4 + (nt & 1) * 2;
                    mma_fp16(c + (mt * 4 + nt) * 4, ah + 4 * mt, bh[bi], bh[bi + 1]);
                }
        }
    }
    __syncthreads();

    // ---- epilogue ----
    float* acc_s  = (float*)smem;                 // 128 x 132
    float* node_t = (float*)(smem + NODET_OFF);   // [o][n] pad 33
    int*   nidx_s = (int*)(smem + NIDX_OFF);

#pragma unroll
    for (int mt = 0; mt < 4; mt++)
#pragma unroll
        for (int nt = 0; nt < 4; nt++) {
            int m = wm * 64 + mt * 16 + (lane >> 2);
            int o = wn * 32 + nt * 8 + 2 * (lane & 3);
            const float* cf = c + (mt * 4 + nt) * 4;
            acc_s[o * 132 + m]           = cf[0];
            acc_s[(o + 1) * 132 + m]     = cf[1];
            acc_s[o * 132 + m + 8]       = cf[2];
            acc_s[(o + 1) * 132 + m + 8] = cf[3];
        }

    for (int i = tid; i < 4096; i += 256) {
        int o = i >> 5, n = i & 31;
        node_t[o * 33 + n] = g_out_node_t[b * 4096 + i];
    }
    if (tid < 128) {
        int bv = board[(b * 128 + h) * 128 + tid];
        nidx_s[tid] = (bv >= 0 && bv < 32) ? c2n[bv] : -1;
    }
    __syncthreads();

#pragma unroll
    for (int it = 0; it < 16; it++) {
        int o = wid + it * 8;
        float bo = conv_b[o];
        float4 a4 = *(const float4*)&acc_s[o * 132 + 4 * lane];
        int4  nd  = *(const int4*)&nidx_s[4 * lane];
        const float* nr = node_t + o * 33;
        float4 v;
        v.x = a4.x + bo + (nd.x >= 0 ? nr[nd.x] : 0.f);
        v.y = a4.y + bo + (nd.y >= 0 ? nr[nd.y] : 0.f);
        v.z = a4.z + bo + (nd.z >= 0 ? nr[nd.z] : 0.f);
        v.w = a4.w + bo + (nd.w >= 0 ? nr[nd.w] : 0.f);
        *(float4*)(out + (((size_t)(b * 128 + o) * 128) + h) * 128 + 4 * lane) = v;
    }
}

// ---------------------------------------------------------------------------
extern "C" void kernel_launch(void* const* d_in, const int* in_sizes, int n_in,
                              void* d_out, int out_size) {
    const int*   game_board   = (const int*)  d_in[0];
    const float* state        = (const float*)d_in[1];
    const float* node_embeds  = (const float*)d_in[2];
    const float* goal_embed   = (const float*)d_in[3];
    const int*   char_to_node = (const int*)  d_in[4];
    const float* conv_w       = (const float*)d_in[5];
    const float* conv_b       = (const float*)d_in[6];
    const float* wQ           = (const float*)d_in[7];
    const float* wK           = (const float*)d_in[8];
    const float* wV           = (const float*)d_in[9];
    const float* final_w      = (const float*)d_in[10];
    const float* final_b      = (const float*)d_in[11];
    float* out = (float*)d_out;

    cudaFuncSetAttribute(conv_mma_kernel,
                         cudaFuncAttributeMaxDynamicSharedMemorySize, CONV_SMEM);

    split_state_kernel<<<dim3(4, 128, 32), 256>>>(state);
    split_w_kernel<<<(9 * 128 * 64 + 255) / 256, 256>>>(conv_w);
    attn_pre1<<<16, 256>>>(node_embeds, wQ, wK, wV);
    attn_pre2<<<5, 256>>>(final_w);
    attn_perb<<<32, 256>>>(goal_embed, wQ, wK, wV, final_w, final_b);
    conv_mma_kernel<<<dim3(128, 32), 256, CONV_SMEM>>>(conv_b, game_board,
                                                       char_to_node, out);
}